// round 1
// baseline (speedup 1.0000x reference)
#include <cuda_runtime.h>
#include <cuda_bf16.h>

// RoIAlign: feat [4,256,100,100] f32, rois [512,5] f32 -> out [512,256,7,7] f32
// SPATIAL_SCALE=0.25, SAMPLING_RATIO=2, ALIGNED=true, OUT 7x7.

#define FH 100
#define FW 100
#define FC 256
#define OUTHW 49   // 7*7
#define NTAP 16    // 2x2 samples * 4 bilinear corners

__global__ __launch_bounds__(256) void roialign_kernel(
    const float* __restrict__ feat,
    const float* __restrict__ rois,
    float* __restrict__ out)
{
    // taps laid out [tap][pixel] so consecutive-pixel lanes hit consecutive 8B words
    __shared__ int2 s_tap[NTAP * OUTHW];  // .x = element offset in channel plane, .y = weight bits
    __shared__ int s_b;

    const int k   = blockIdx.x;
    const int tid = threadIdx.x;

    if (tid == 0) s_b = (int)rois[k * 5 + 0];

    if (tid < OUTHW) {
        const float x1 = rois[k * 5 + 1];
        const float y1 = rois[k * 5 + 2];
        const float x2 = rois[k * 5 + 3];
        const float y2 = rois[k * 5 + 4];

        const float sw = x1 * 0.25f - 0.5f;
        const float sh = y1 * 0.25f - 0.5f;
        const float ew = x2 * 0.25f - 0.5f;
        const float eh = y2 * 0.25f - 0.5f;
        const float bw = (ew - sw) * (1.0f / 7.0f);
        const float bh = (eh - sh) * (1.0f / 7.0f);

        const int p  = tid;
        const int ph = p / 7;
        const int pw = p - ph * 7;

        int   yli[2], yhi[2], xli[2], xhi[2];
        float lyv[2], hyv[2], lxv[2], hxv[2];

        #pragma unroll
        for (int i = 0; i < 2; i++) {
            // y sample
            float y = sh + (float)ph * bh + ((float)i + 0.5f) * (bh * 0.5f);
            y = fmaxf(y, 0.0f);
            int yl = (int)y;
            int yh = (yl >= FH - 1) ? (FH - 1) : (yl + 1);
            yl     = (yl >= FH - 1) ? (FH - 1) : yl;
            float ly = y - (float)yl;
            yli[i] = yl; yhi[i] = yh; lyv[i] = ly; hyv[i] = 1.0f - ly;

            // x sample
            float x = sw + (float)pw * bw + ((float)i + 0.5f) * (bw * 0.5f);
            x = fmaxf(x, 0.0f);
            int xl = (int)x;
            int xh = (xl >= FW - 1) ? (FW - 1) : (xl + 1);
            xl     = (xl >= FW - 1) ? (FW - 1) : xl;
            float lx = x - (float)xl;
            xli[i] = xl; xhi[i] = xh; lxv[i] = lx; hxv[i] = 1.0f - lx;
        }

        int t = 0;
        #pragma unroll
        for (int iy = 0; iy < 2; iy++) {
            #pragma unroll
            for (int ix = 0; ix < 2; ix++) {
                // count = SR*SR = 4 folded into the weights
                s_tap[(t + 0) * OUTHW + p] = make_int2(yli[iy] * FW + xli[ix],
                                                       __float_as_int(0.25f * hyv[iy] * hxv[ix]));
                s_tap[(t + 1) * OUTHW + p] = make_int2(yli[iy] * FW + xhi[ix],
                                                       __float_as_int(0.25f * hyv[iy] * lxv[ix]));
                s_tap[(t + 2) * OUTHW + p] = make_int2(yhi[iy] * FW + xli[ix],
                                                       __float_as_int(0.25f * lyv[iy] * hxv[ix]));
                s_tap[(t + 3) * OUTHW + p] = make_int2(yhi[iy] * FW + xhi[ix],
                                                       __float_as_int(0.25f * lyv[iy] * lxv[ix]));
                t += 4;
            }
        }
    }
    __syncthreads();

    const float* fb = feat + (size_t)s_b * (FC * FH * FW);
    float*       ob = out  + (size_t)k   * (FC * OUTHW);

    // idx = c*49 + p walks 0..12543 in steps of 256; 256 = 5*49 + 11
    int c = tid / OUTHW;
    int p = tid - c * OUTHW;

    #pragma unroll 1
    for (int it = 0; it < 49; it++) {
        const float* fc = fb + c * (FH * FW);
        float acc = 0.0f;
        #pragma unroll
        for (int t = 0; t < NTAP; t++) {
            int2 tap = s_tap[t * OUTHW + p];
            acc = fmaf(__int_as_float(tap.y), __ldg(fc + tap.x), acc);
        }
        ob[c * OUTHW + p] = acc;

        p += 11; c += 5;
        if (p >= OUTHW) { p -= OUTHW; c += 1; }
    }
}

extern "C" void kernel_launch(void* const* d_in, const int* in_sizes, int n_in,
                              void* d_out, int out_size)
{
    const float* feat = (const float*)d_in[0];
    const float* rois = (const float*)d_in[1];
    float*       out  = (float*)d_out;

    const int K = in_sizes[1] / 5;  // 512
    roialign_kernel<<<K, 256>>>(feat, rois, out);
}

// round 2
// speedup vs baseline: 1.0599x; 1.0599x over previous
#include <cuda_runtime.h>
#include <cuda_bf16.h>

// RoIAlign: feat [4,256,100,100] f32, rois [512,5] f32 -> out [512,256,7,7] f32
// SPATIAL_SCALE=0.25, SAMPLING_RATIO=2, ALIGNED=true, OUT 7x7.
//
// Strategy: one block per RoI. The sample footprint is a bounding box of at
// most ~25x25 feature pixels. Stage 16 channels' regions in SMEM with
// coalesced row loads, then each thread (fixed output pixel p, channel lane
// c_sub) computes outputs from SMEM with its 16 taps held in registers.

#define FH 100
#define FW 100
#define FC 256
#define OUTHW 49     // 7*7
#define NTAP 16      // 2x2 samples * 4 bilinear corners
#define RS 27        // region row stride / max region dim (odd -> low bank conflicts)
#define CHUNK 16     // channels per SMEM chunk
#define NCHUNK (FC / CHUNK)

__global__ __launch_bounds__(256) void roialign_kernel(
    const float* __restrict__ feat,
    const float* __restrict__ rois,
    float* __restrict__ out)
{
    __shared__ float s_reg[CHUNK * RS * RS];  // 16 * 729 * 4 = 46656 B

    const int k    = blockIdx.x;
    const int tid  = threadIdx.x;
    const int wid  = tid >> 5;
    const int lane = tid & 31;

    // --- RoI params (broadcast loads) ---
    const int   b  = (int)__ldg(rois + k * 5 + 0);
    const float x1 = __ldg(rois + k * 5 + 1);
    const float y1 = __ldg(rois + k * 5 + 2);
    const float x2 = __ldg(rois + k * 5 + 3);
    const float y2 = __ldg(rois + k * 5 + 4);

    const float sw = x1 * 0.25f - 0.5f;
    const float sh = y1 * 0.25f - 0.5f;
    const float bw = (x2 * 0.25f - 0.5f - sw) * (1.0f / 7.0f);
    const float bh = (y2 * 0.25f - 0.5f - sh) * (1.0f / 7.0f);

    // --- region bounds (monotone in ph/pw: first sample -> min, last -> max) ---
    float ya = fmaxf(sh + 0.25f * bh, 0.0f);
    int   y0 = (int)ya;          if (y0 >= FH - 1) y0 = FH - 1;
    float yb = fmaxf(sh + 6.75f * bh, 0.0f);
    int   yl_end = (int)yb;
    int   y1i = (yl_end >= FH - 1) ? (FH - 1) : (yl_end + 1);
    int   h = y1i - y0 + 1;      if (h > RS) h = RS;

    float xa = fmaxf(sw + 0.25f * bw, 0.0f);
    int   x0 = (int)xa;          if (x0 >= FW - 1) x0 = FW - 1;
    float xb = fmaxf(sw + 6.75f * bw, 0.0f);
    int   xl_end = (int)xb;
    int   x1i = (xl_end >= FW - 1) ? (FW - 1) : (xl_end + 1);
    int   w = x1i - x0 + 1;      if (w > RS) w = RS;

    // --- per-thread taps in registers (thread <-> fixed pixel p, channel lane c_sub) ---
    int   toff[NTAP];
    float twgt[NTAP];
    const int c_sub = tid / OUTHW;            // 0..4 active (tid < 245)
    const int p     = tid - c_sub * OUTHW;
    const bool active = (tid < 5 * OUTHW);

    if (active) {
        const int ph = p / 7;
        const int pw = p - ph * 7;

        int   yli[2], yhi[2], xli[2], xhi[2];
        float lyv[2], hyv[2], lxv[2], hxv[2];

        #pragma unroll
        for (int i = 0; i < 2; i++) {
            float y = sh + (float)ph * bh + ((float)i + 0.5f) * (bh * 0.5f);
            y = fmaxf(y, 0.0f);
            int yl = (int)y;
            int yh = (yl >= FH - 1) ? (FH - 1) : (yl + 1);
            yl     = (yl >= FH - 1) ? (FH - 1) : yl;
            float ly = y - (float)yl;
            yli[i] = yl - y0; yhi[i] = yh - y0; lyv[i] = ly; hyv[i] = 1.0f - ly;

            float x = sw + (float)pw * bw + ((float)i + 0.5f) * (bw * 0.5f);
            x = fmaxf(x, 0.0f);
            int xl = (int)x;
            int xh = (xl >= FW - 1) ? (FW - 1) : (xl + 1);
            xl     = (xl >= FW - 1) ? (FW - 1) : xl;
            float lx = x - (float)xl;
            xli[i] = xl - x0; xhi[i] = xh - x0; lxv[i] = lx; hxv[i] = 1.0f - lx;
        }

        int t = 0;
        #pragma unroll
        for (int iy = 0; iy < 2; iy++) {
            #pragma unroll
            for (int ix = 0; ix < 2; ix++) {
                toff[t + 0] = yli[iy] * RS + xli[ix];
                twgt[t + 0] = 0.25f * hyv[iy] * hxv[ix];
                toff[t + 1] = yli[iy] * RS + xhi[ix];
                twgt[t + 1] = 0.25f * hyv[iy] * lxv[ix];
                toff[t + 2] = yhi[iy] * RS + xli[ix];
                twgt[t + 2] = 0.25f * lyv[iy] * hxv[ix];
                toff[t + 3] = yhi[iy] * RS + xhi[ix];
                twgt[t + 3] = 0.25f * lyv[iy] * lxv[ix];
                t += 4;
            }
        }
    }

    const float* fb = feat + (size_t)b * (FC * FH * FW);
    float*       ob = out  + (size_t)k * (FC * OUTHW);

    for (int cc = 0; cc < NCHUNK; cc++) {
        // --- stage 16 channels' regions: warp handles 2 channels, lanes = cols ---
        #pragma unroll
        for (int j = 0; j < 2; j++) {
            const int cl = wid * 2 + j;
            const float* src = fb + (size_t)(cc * CHUNK + cl) * (FH * FW) + y0 * FW + x0;
            float* dst = s_reg + cl * (RS * RS);
            if (lane < w) {
                #pragma unroll 4
                for (int r = 0; r < h; r++)
                    dst[r * RS + lane] = __ldg(src + r * FW + lane);
            }
        }
        __syncthreads();

        // --- compute from SMEM ---
        if (active) {
            #pragma unroll 1
            for (int cl = c_sub; cl < CHUNK; cl += 5) {
                const float* rg = s_reg + cl * (RS * RS);
                float acc = 0.0f;
                #pragma unroll
                for (int t = 0; t < NTAP; t++)
                    acc = fmaf(twgt[t], rg[toff[t]], acc);
                ob[(cc * CHUNK + cl) * OUTHW + p] = acc;
            }
        }
        __syncthreads();
    }
}

extern "C" void kernel_launch(void* const* d_in, const int* in_sizes, int n_in,
                              void* d_out, int out_size)
{
    const float* feat = (const float*)d_in[0];
    const float* rois = (const float*)d_in[1];
    float*       out  = (float*)d_out;

    const int K = in_sizes[1] / 5;  // 512
    roialign_kernel<<<K, 256>>>(feat, rois, out);
}

// round 3
// speedup vs baseline: 1.0633x; 1.0032x over previous
#include <cuda_runtime.h>
#include <cuda_bf16.h>

// RoIAlign: feat [4,256,100,100] f32, rois [512,5] f32 -> out [512,256,7,7] f32
// SPATIAL_SCALE=0.25, SAMPLING_RATIO=2, ALIGNED=true, OUT 7x7.
//
// Strategy: one block per RoI. The sample footprint is a bounding box of at
// most ~25x25 feature pixels. Stage 16 channels' regions in SMEM with
// coalesced row loads, then each thread (fixed output pixel p, channel lane
// c_sub) computes outputs from SMEM with its 16 taps held in registers.

#define FH 100
#define FW 100
#define FC 256
#define OUTHW 49     // 7*7
#define NTAP 16      // 2x2 samples * 4 bilinear corners
#define RS 27        // region row stride / max region dim (odd -> low bank conflicts)
#define CHUNK 16     // channels per SMEM chunk
#define NCHUNK (FC / CHUNK)

__global__ __launch_bounds__(256) void roialign_kernel(
    const float* __restrict__ feat,
    const float* __restrict__ rois,
    float* __restrict__ out)
{
    __shared__ float s_reg[CHUNK * RS * RS];  // 16 * 729 * 4 = 46656 B

    const int k    = blockIdx.x;
    const int tid  = threadIdx.x;
    const int wid  = tid >> 5;
    const int lane = tid & 31;

    // --- RoI params (broadcast loads) ---
    const int   b  = (int)__ldg(rois + k * 5 + 0);
    const float x1 = __ldg(rois + k * 5 + 1);
    const float y1 = __ldg(rois + k * 5 + 2);
    const float x2 = __ldg(rois + k * 5 + 3);
    const float y2 = __ldg(rois + k * 5 + 4);

    const float sw = x1 * 0.25f - 0.5f;
    const float sh = y1 * 0.25f - 0.5f;
    const float bw = (x2 * 0.25f - 0.5f - sw) * (1.0f / 7.0f);
    const float bh = (y2 * 0.25f - 0.5f - sh) * (1.0f / 7.0f);

    // --- region bounds (monotone in ph/pw: first sample -> min, last -> max) ---
    float ya = fmaxf(sh + 0.25f * bh, 0.0f);
    int   y0 = (int)ya;          if (y0 >= FH - 1) y0 = FH - 1;
    float yb = fmaxf(sh + 6.75f * bh, 0.0f);
    int   yl_end = (int)yb;
    int   y1i = (yl_end >= FH - 1) ? (FH - 1) : (yl_end + 1);
    int   h = y1i - y0 + 1;      if (h > RS) h = RS;

    float xa = fmaxf(sw + 0.25f * bw, 0.0f);
    int   x0 = (int)xa;          if (x0 >= FW - 1) x0 = FW - 1;
    float xb = fmaxf(sw + 6.75f * bw, 0.0f);
    int   xl_end = (int)xb;
    int   x1i = (xl_end >= FW - 1) ? (FW - 1) : (xl_end + 1);
    int   w = x1i - x0 + 1;      if (w > RS) w = RS;

    // --- per-thread taps in registers (thread <-> fixed pixel p, channel lane c_sub) ---
    int   toff[NTAP];
    float twgt[NTAP];
    const int c_sub = tid / OUTHW;            // 0..4 active (tid < 245)
    const int p     = tid - c_sub * OUTHW;
    const bool active = (tid < 5 * OUTHW);

    if (active) {
        const int ph = p / 7;
        const int pw = p - ph * 7;

        int   yli[2], yhi[2], xli[2], xhi[2];
        float lyv[2], hyv[2], lxv[2], hxv[2];

        #pragma unroll
        for (int i = 0; i < 2; i++) {
            float y = sh + (float)ph * bh + ((float)i + 0.5f) * (bh * 0.5f);
            y = fmaxf(y, 0.0f);
            int yl = (int)y;
            int yh = (yl >= FH - 1) ? (FH - 1) : (yl + 1);
            yl     = (yl >= FH - 1) ? (FH - 1) : yl;
            float ly = y - (float)yl;
            yli[i] = yl - y0; yhi[i] = yh - y0; lyv[i] = ly; hyv[i] = 1.0f - ly;

            float x = sw + (float)pw * bw + ((float)i + 0.5f) * (bw * 0.5f);
            x = fmaxf(x, 0.0f);
            int xl = (int)x;
            int xh = (xl >= FW - 1) ? (FW - 1) : (xl + 1);
            xl     = (xl >= FW - 1) ? (FW - 1) : xl;
            float lx = x - (float)xl;
            xli[i] = xl - x0; xhi[i] = xh - x0; lxv[i] = lx; hxv[i] = 1.0f - lx;
        }

        int t = 0;
        #pragma unroll
        for (int iy = 0; iy < 2; iy++) {
            #pragma unroll
            for (int ix = 0; ix < 2; ix++) {
                toff[t + 0] = yli[iy] * RS + xli[ix];
                twgt[t + 0] = 0.25f * hyv[iy] * hxv[ix];
                toff[t + 1] = yli[iy] * RS + xhi[ix];
                twgt[t + 1] = 0.25f * hyv[iy] * lxv[ix];
                toff[t + 2] = yhi[iy] * RS + xli[ix];
                twgt[t + 2] = 0.25f * lyv[iy] * hxv[ix];
                toff[t + 3] = yhi[iy] * RS + xhi[ix];
                twgt[t + 3] = 0.25f * lyv[iy] * lxv[ix];
                t += 4;
            }
        }
    }

    const float* fb = feat + (size_t)b * (FC * FH * FW);
    float*       ob = out  + (size_t)k * (FC * OUTHW);

    for (int cc = 0; cc < NCHUNK; cc++) {
        // --- stage 16 channels' regions: warp handles 2 channels, lanes = cols ---
        #pragma unroll
        for (int j = 0; j < 2; j++) {
            const int cl = wid * 2 + j;
            const float* src = fb + (size_t)(cc * CHUNK + cl) * (FH * FW) + y0 * FW + x0;
            float* dst = s_reg + cl * (RS * RS);
            if (lane < w) {
                #pragma unroll 4
                for (int r = 0; r < h; r++)
                    dst[r * RS + lane] = __ldg(src + r * FW + lane);
            }
        }
        __syncthreads();

        // --- compute from SMEM ---
        if (active) {
            #pragma unroll 1
            for (int cl = c_sub; cl < CHUNK; cl += 5) {
                const float* rg = s_reg + cl * (RS * RS);
                float acc = 0.0f;
                #pragma unroll
                for (int t = 0; t < NTAP; t++)
                    acc = fmaf(twgt[t], rg[toff[t]], acc);
                ob[(cc * CHUNK + cl) * OUTHW + p] = acc;
            }
        }
        __syncthreads();
    }
}

extern "C" void kernel_launch(void* const* d_in, const int* in_sizes, int n_in,
                              void* d_out, int out_size)
{
    const float* feat = (const float*)d_in[0];
    const float* rois = (const float*)d_in[1];
    float*       out  = (float*)d_out;

    const int K = in_sizes[1] / 5;  // 512
    roialign_kernel<<<K, 256>>>(feat, rois, out);
}

// round 4
// speedup vs baseline: 1.4126x; 1.3285x over previous
#include <cuda_runtime.h>
#include <cuda_bf16.h>
#include <cstdint>

// RoIAlign: feat [4,256,100,100] f32, rois [512,5] f32 -> out [512,256,7,7] f32
// SPATIAL_SCALE=0.25, SAMPLING_RATIO=2, ALIGNED=true, OUT 7x7.
//
// One block per (RoI, channel-half). Region bounding box <= 25x25.
// Double-buffered cp.async staging of 8 channels/chunk overlapped with
// compute; taps (offset, weight) held in registers per thread.

#define FH 100
#define FW 100
#define FC 256
#define OUTHW 49
#define NTAP 16
#define RS 25            // max region dim; odd stride -> low bank conflicts
#define CHUNK 8          // channels per stage
#define CSPLIT 2         // channel-split blocks per RoI
#define CPB (FC / CSPLIT)     // 128 channels per block
#define NCHUNK (CPB / CHUNK)  // 16

#define CP_COMMIT asm volatile("cp.async.commit_group;\n" ::)
#define CP_WAIT(n) asm volatile("cp.async.wait_group %0;\n" :: "n"(n))

__device__ __forceinline__ void cp4(uint32_t saddr, const float* g) {
    asm volatile("cp.async.ca.shared.global [%0], [%1], 4;\n" :: "r"(saddr), "l"(g));
}

__global__ __launch_bounds__(256) void roialign_kernel(
    const float* __restrict__ feat,
    const float* __restrict__ rois,
    float* __restrict__ out)
{
    __shared__ float s_reg[2][CHUNK][RS * RS];  // 2*8*625*4 = 40000 B

    const int k    = blockIdx.x;
    const int cbase = blockIdx.y * CPB;
    const int tid  = threadIdx.x;
    const int wid  = tid >> 5;
    const int lane = tid & 31;

    // --- RoI params (broadcast) ---
    const int   b  = (int)__ldg(rois + k * 5 + 0);
    const float x1 = __ldg(rois + k * 5 + 1);
    const float y1 = __ldg(rois + k * 5 + 2);
    const float x2 = __ldg(rois + k * 5 + 3);
    const float y2 = __ldg(rois + k * 5 + 4);

    const float sw = x1 * 0.25f - 0.5f;
    const float sh = y1 * 0.25f - 0.5f;
    const float bw = (x2 * 0.25f - 0.5f - sw) * (1.0f / 7.0f);
    const float bh = (y2 * 0.25f - 0.5f - sh) * (1.0f / 7.0f);

    // --- region bounds (samples are monotone in ph/pw) ---
    float ya = fmaxf(sh + 0.25f * bh, 0.0f);
    int   y0 = (int)ya;          if (y0 >= FH - 1) y0 = FH - 1;
    float yb = fmaxf(sh + 6.75f * bh, 0.0f);
    int   yle = (int)yb;
    int   y1i = (yle >= FH - 1) ? (FH - 1) : (yle + 1);
    int   h = y1i - y0 + 1;      if (h > RS) h = RS;

    float xa = fmaxf(sw + 0.25f * bw, 0.0f);
    int   x0 = (int)xa;          if (x0 >= FW - 1) x0 = FW - 1;
    float xb = fmaxf(sw + 6.75f * bw, 0.0f);
    int   xle = (int)xb;
    int   x1i = (xle >= FW - 1) ? (FW - 1) : (xle + 1);
    int   w = x1i - x0 + 1;      if (w > RS) w = RS;

    // --- per-thread taps in registers ---
    int   toff[NTAP];
    float twgt[NTAP];
    const int c_sub = tid / OUTHW;          // 0..4 active (tid < 245)
    const int p     = tid - c_sub * OUTHW;
    const bool active = (tid < 5 * OUTHW);

    if (active) {
        const int ph = p / 7;
        const int pw = p - ph * 7;

        int   yli[2], yhi[2], xli[2], xhi[2];
        float lyv[2], hyv[2], lxv[2], hxv[2];

        #pragma unroll
        for (int i = 0; i < 2; i++) {
            float y = sh + (float)ph * bh + ((float)i + 0.5f) * (bh * 0.5f);
            y = fmaxf(y, 0.0f);
            int yl = (int)y;
            int yh = (yl >= FH - 1) ? (FH - 1) : (yl + 1);
            yl     = (yl >= FH - 1) ? (FH - 1) : yl;
            float ly = y - (float)yl;
            yli[i] = yl - y0; yhi[i] = yh - y0; lyv[i] = ly; hyv[i] = 1.0f - ly;

            float x = sw + (float)pw * bw + ((float)i + 0.5f) * (bw * 0.5f);
            x = fmaxf(x, 0.0f);
            int xl = (int)x;
            int xh = (xl >= FW - 1) ? (FW - 1) : (xl + 1);
            xl     = (xl >= FW - 1) ? (FW - 1) : xl;
            float lx = x - (float)xl;
            xli[i] = xl - x0; xhi[i] = xh - x0; lxv[i] = lx; hxv[i] = 1.0f - lx;
        }

        int t = 0;
        #pragma unroll
        for (int iy = 0; iy < 2; iy++) {
            #pragma unroll
            for (int ix = 0; ix < 2; ix++) {
                toff[t + 0] = yli[iy] * RS + xli[ix];
                twgt[t + 0] = 0.25f * hyv[iy] * hxv[ix];
                toff[t + 1] = yli[iy] * RS + xhi[ix];
                twgt[t + 1] = 0.25f * hyv[iy] * lxv[ix];
                toff[t + 2] = yhi[iy] * RS + xli[ix];
                twgt[t + 2] = 0.25f * lyv[iy] * hxv[ix];
                toff[t + 3] = yhi[iy] * RS + xhi[ix];
                twgt[t + 3] = 0.25f * lyv[iy] * lxv[ix];
                t += 4;
            }
        }
    }

    const float* fb = feat + (size_t)b * (FC * FH * FW)
                           + (size_t)cbase * (FH * FW) + y0 * FW + x0;
    float*       ob = out  + (size_t)k * (FC * OUTHW) + cbase * OUTHW;

    // warp wid stages channel wid of each chunk; lanes = columns
    const uint32_t s0 = (uint32_t)__cvta_generic_to_shared(&s_reg[0][wid][0]) + lane * 4u;
    const uint32_t s1 = (uint32_t)__cvta_generic_to_shared(&s_reg[1][wid][0]) + lane * 4u;
    const bool stager = (lane < w);

    // --- prologue: stage chunk 0 into buffer 0 ---
    {
        const float* src = fb + (size_t)wid * (FH * FW) + lane;
        if (stager) {
            #pragma unroll 4
            for (int r = 0; r < h; r++)
                cp4(s0 + r * (RS * 4), src + r * FW);
        }
        CP_COMMIT;
    }

    #pragma unroll 1
    for (int cc = 0; cc < NCHUNK; cc++) {
        if (cc + 1 < NCHUNK) {
            // stage next chunk into the other buffer
            const float* src = fb + (size_t)((cc + 1) * CHUNK + wid) * (FH * FW) + lane;
            const uint32_t sb = ((cc + 1) & 1) ? s1 : s0;
            if (stager) {
                #pragma unroll 4
                for (int r = 0; r < h; r++)
                    cp4(sb + r * (RS * 4), src + r * FW);
            }
            CP_COMMIT;
            CP_WAIT(1);   // chunk cc complete
        } else {
            CP_WAIT(0);
        }
        __syncthreads();

        if (active) {
            const int buf = cc & 1;
            #pragma unroll
            for (int j = 0; j < 2; j++) {
                const int cl = c_sub + 5 * j;
                if (cl < CHUNK) {
                    const float* rg = &s_reg[buf][cl][0];
                    float acc = 0.0f;
                    #pragma unroll
                    for (int t = 0; t < NTAP; t++)
                        acc = fmaf(twgt[t], rg[toff[t]], acc);
                    ob[(cc * CHUNK + cl) * OUTHW + p] = acc;
                }
            }
        }
        __syncthreads();  // buffer (cc&1) free for stage(cc+2)
    }
}

extern "C" void kernel_launch(void* const* d_in, const int* in_sizes, int n_in,
                              void* d_out, int out_size)
{
    const float* feat = (const float*)d_in[0];
    const float* rois = (const float*)d_in[1];
    float*       out  = (float*)d_out;

    // prefer max shared-memory carveout so 4 CTAs (160 KB) fit per SM
    cudaFuncSetAttribute(roialign_kernel,
                         cudaFuncAttributePreferredSharedMemoryCarveout, 100);

    const int K = in_sizes[1] / 5;  // 512
    dim3 grid(K, CSPLIT);
    roialign_kernel<<<grid, 256>>>(feat, rois, out);
}

// round 5
// speedup vs baseline: 1.6240x; 1.1496x over previous
#include <cuda_runtime.h>
#include <cuda_bf16.h>
#include <cstdint>

// RoIAlign: feat [4,256,100,100] f32, rois [512,5] f32 -> out [512,256,7,7] f32
// SPATIAL_SCALE=0.25, SAMPLING_RATIO=2, ALIGNED=true, OUT 7x7.
//
// One block per (RoI, channel-quarter). Region bbox <= 25 rows x 25 cols,
// staged with 16B cp.async (x start aligned down to 4 floats, row stride 28),
// double-buffered 8-channel chunks overlapped with compute. Taps in registers.

#define FH 100
#define FW 100
#define FC 256
#define OUTHW 49
#define NTAP 16
#define RROWS 25         // max region rows
#define RSTRIDE 28       // region row stride in floats (mult of 4 for 16B cp.async)
#define CHUNK 8          // channels per stage
#define CSPLIT 4         // channel-split blocks per RoI
#define CPB (FC / CSPLIT)     // 64 channels per block
#define NCHUNK (CPB / CHUNK)  // 8

#define CP_COMMIT asm volatile("cp.async.commit_group;\n" ::)
#define CP_WAIT(n) asm volatile("cp.async.wait_group %0;\n" :: "n"(n))

__device__ __forceinline__ void cp16(uint32_t saddr, const float* g) {
    asm volatile("cp.async.cg.shared.global [%0], [%1], 16;\n" :: "r"(saddr), "l"(g));
}

__global__ __launch_bounds__(256) void roialign_kernel(
    const float* __restrict__ feat,
    const float* __restrict__ rois,
    float* __restrict__ out)
{
    __shared__ float s_reg[2][CHUNK][RROWS * RSTRIDE];  // 2*8*700*4 = 44800 B

    const int k     = blockIdx.x;
    const int cbase = blockIdx.y * CPB;
    const int tid   = threadIdx.x;
    const int wid   = tid >> 5;
    const int lane  = tid & 31;

    // --- RoI params (broadcast) ---
    const int   b  = (int)__ldg(rois + k * 5 + 0);
    const float x1 = __ldg(rois + k * 5 + 1);
    const float y1 = __ldg(rois + k * 5 + 2);
    const float x2 = __ldg(rois + k * 5 + 3);
    const float y2 = __ldg(rois + k * 5 + 4);

    const float sw = x1 * 0.25f - 0.5f;
    const float sh = y1 * 0.25f - 0.5f;
    const float bw = (x2 * 0.25f - 0.5f - sw) * (1.0f / 7.0f);
    const float bh = (y2 * 0.25f - 0.5f - sh) * (1.0f / 7.0f);

    // --- region bounds (samples monotone in ph/pw) ---
    float ya = fmaxf(sh + 0.25f * bh, 0.0f);
    int   y0 = (int)ya;          if (y0 >= FH - 1) y0 = FH - 1;
    float yb = fmaxf(sh + 6.75f * bh, 0.0f);
    int   yle = (int)yb;
    int   y1i = (yle >= FH - 1) ? (FH - 1) : (yle + 1);
    int   h = y1i - y0 + 1;      if (h > RROWS) h = RROWS;

    float xa = fmaxf(sw + 0.25f * bw, 0.0f);
    int   x0 = (int)xa;          if (x0 >= FW - 1) x0 = FW - 1;
    float xb = fmaxf(sw + 6.75f * bw, 0.0f);
    int   xle = (int)xb;
    int   x1i = (xle >= FW - 1) ? (FW - 1) : (xle + 1);

    const int x0a  = x0 & ~3;                 // 16B-aligned region start
    int       wext = x1i - x0a + 1;
    if (wext > RSTRIDE) wext = RSTRIDE;
    const int w4   = (wext + 3) >> 2;         // 16B chunks per row (<=7)

    // --- per-thread taps in registers ---
    int   toff[NTAP];
    float twgt[NTAP];
    const int c_sub = tid / OUTHW;            // 0..4 active (tid < 245)
    const int p     = tid - c_sub * OUTHW;
    const bool active = (tid < 5 * OUTHW);

    if (active) {
        const int ph = p / 7;
        const int pw = p - ph * 7;

        int   yli[2], yhi[2], xli[2], xhi[2];
        float lyv[2], hyv[2], lxv[2], hxv[2];

        #pragma unroll
        for (int i = 0; i < 2; i++) {
            float y = sh + (float)ph * bh + ((float)i + 0.5f) * (bh * 0.5f);
            y = fmaxf(y, 0.0f);
            int yl = (int)y;
            int yh = (yl >= FH - 1) ? (FH - 1) : (yl + 1);
            yl     = (yl >= FH - 1) ? (FH - 1) : yl;
            float ly = y - (float)yl;
            yli[i] = yl - y0; yhi[i] = yh - y0; lyv[i] = ly; hyv[i] = 1.0f - ly;

            float x = sw + (float)pw * bw + ((float)i + 0.5f) * (bw * 0.5f);
            x = fmaxf(x, 0.0f);
            int xl = (int)x;
            int xh = (xl >= FW - 1) ? (FW - 1) : (xl + 1);
            xl     = (xl >= FW - 1) ? (FW - 1) : xl;
            float lx = x - (float)xl;
            xli[i] = xl - x0a; xhi[i] = xh - x0a; lxv[i] = lx; hxv[i] = 1.0f - lx;
        }

        int t = 0;
        #pragma unroll
        for (int iy = 0; iy < 2; iy++) {
            #pragma unroll
            for (int ix = 0; ix < 2; ix++) {
                toff[t + 0] = yli[iy] * RSTRIDE + xli[ix];
                twgt[t + 0] = 0.25f * hyv[iy] * hxv[ix];
                toff[t + 1] = yli[iy] * RSTRIDE + xhi[ix];
                twgt[t + 1] = 0.25f * hyv[iy] * lxv[ix];
                toff[t + 2] = yhi[iy] * RSTRIDE + xli[ix];
                twgt[t + 2] = 0.25f * lyv[iy] * hxv[ix];
                toff[t + 3] = yhi[iy] * RSTRIDE + xhi[ix];
                twgt[t + 3] = 0.25f * lyv[iy] * lxv[ix];
                t += 4;
            }
        }
    }

    const float* fb = feat + (size_t)b * (FC * FH * FW)
                           + (size_t)cbase * (FH * FW) + y0 * FW + x0a;
    float*       ob = out  + (size_t)k * (FC * OUTHW) + cbase * OUTHW;

    // staging lane mapping: flatten (row, chunk) over 32 lanes
    const int r_init = lane / w4;            // one-time small div
    const int c_init = lane - r_init * w4;
    const int q32    = 32 / w4;
    const int rem32  = 32 - q32 * w4;

    const uint32_t sbase = (uint32_t)__cvta_generic_to_shared(&s_reg[0][0][0]);
    const uint32_t schan = sbase + wid * (RROWS * RSTRIDE * 4);
    const uint32_t sbufsz = CHUNK * RROWS * RSTRIDE * 4;

    // --- stage one chunk: warp wid stages channel (cc*CHUNK + wid) ---
    auto stage = [&](int cc) {
        const float* g = fb + (size_t)(cc * CHUNK + wid) * (FH * FW);
        const uint32_t sb = schan + (cc & 1) * sbufsz;
        int r = r_init, c = c_init;
        #pragma unroll
        for (int it = 0; it < 6; it++) {
            if (r < h)
                cp16(sb + (r * (RSTRIDE * 4) + (c << 4)), g + r * FW + (c << 2));
            c += rem32;
            int carry = (c >= w4);
            r += q32 + carry;
            if (carry) c -= w4;
        }
        CP_COMMIT;
    };

    stage(0);

    #pragma unroll 1
    for (int cc = 0; cc < NCHUNK; cc++) {
        if (cc + 1 < NCHUNK) {
            stage(cc + 1);
            CP_WAIT(1);        // chunk cc complete
        } else {
            CP_WAIT(0);
        }
        __syncthreads();

        if (active) {
            const int buf = cc & 1;
            #pragma unroll
            for (int j = 0; j < 2; j++) {
                const int cl = c_sub + 5 * j;
                if (cl < CHUNK) {
                    const float* rg = &s_reg[buf][cl][0];
                    float acc = 0.0f;
                    #pragma unroll
                    for (int t = 0; t < NTAP; t++)
                        acc = fmaf(twgt[t], rg[toff[t]], acc);
                    ob[(cc * CHUNK + cl) * OUTHW + p] = acc;
                }
            }
        }
        __syncthreads();       // buffer (cc&1) free for stage(cc+2)
    }
}

extern "C" void kernel_launch(void* const* d_in, const int* in_sizes, int n_in,
                              void* d_out, int out_size)
{
    const float* feat = (const float*)d_in[0];
    const float* rois = (const float*)d_in[1];
    float*       out  = (float*)d_out;

    cudaFuncSetAttribute(roialign_kernel,
                         cudaFuncAttributePreferredSharedMemoryCarveout, 100);

    const int K = in_sizes[1] / 5;  // 512
    dim3 grid(K, CSPLIT);
    roialign_kernel<<<grid, 256>>>(feat, rois, out);
}

// round 6
// speedup vs baseline: 1.8601x; 1.1454x over previous
#include <cuda_runtime.h>
#include <cuda_bf16.h>
#include <cstdint>

// RoIAlign: feat [4,256,100,100] f32, rois [512,5] f32 -> out [512,256,7,7] f32
// SPATIAL_SCALE=0.25, SAMPLING_RATIO=2, ALIGNED=true, OUT 7x7.
//
// One block per (RoI, channel-eighth). Region bbox <= 25x25, staged with 16B
// cp.async (x aligned down to 4 floats, row stride 28), double-buffered
// 8-channel chunks overlapped with compute. Separable taps (4 rows x 4 cols)
// in registers; __launch_bounds__(256,4) -> 64 regs -> 4 CTAs/SM.

#define FH 100
#define FW 100
#define FC 256
#define OUTHW 49
#define RROWS 25         // max region rows
#define RSTRIDE 28       // region row stride in floats (mult of 4)
#define CHUNK 8          // channels per stage
#define CSPLIT 8         // channel-split blocks per RoI
#define CPB (FC / CSPLIT)     // 32 channels per block
#define NCHUNK (CPB / CHUNK)  // 4

#define CP_COMMIT asm volatile("cp.async.commit_group;\n" ::)
#define CP_WAIT(n) asm volatile("cp.async.wait_group %0;\n" :: "n"(n))

__device__ __forceinline__ void cp16(uint32_t saddr, const float* g) {
    asm volatile("cp.async.cg.shared.global [%0], [%1], 16;\n" :: "r"(saddr), "l"(g));
}

__global__ __launch_bounds__(256, 4) void roialign_kernel(
    const float* __restrict__ feat,
    const float* __restrict__ rois,
    float* __restrict__ out)
{
    __shared__ float s_reg[2][CHUNK][RROWS * RSTRIDE];  // 44800 B

    const int k     = blockIdx.x;
    const int cbase = blockIdx.y * CPB;
    const int tid   = threadIdx.x;
    const int wid   = tid >> 5;
    const int lane  = tid & 31;

    // --- RoI params (broadcast) ---
    const int   b  = (int)__ldg(rois + k * 5 + 0);
    const float x1 = __ldg(rois + k * 5 + 1);
    const float y1 = __ldg(rois + k * 5 + 2);
    const float x2 = __ldg(rois + k * 5 + 3);
    const float y2 = __ldg(rois + k * 5 + 4);

    const float sw = x1 * 0.25f - 0.5f;
    const float sh = y1 * 0.25f - 0.5f;
    const float bw = (x2 * 0.25f - 0.5f - sw) * (1.0f / 7.0f);
    const float bh = (y2 * 0.25f - 0.5f - sh) * (1.0f / 7.0f);

    // --- region bounds (samples monotone in ph/pw) ---
    float ya = fmaxf(sh + 0.25f * bh, 0.0f);
    int   y0 = (int)ya;          if (y0 >= FH - 1) y0 = FH - 1;
    float yb = fmaxf(sh + 6.75f * bh, 0.0f);
    int   yle = (int)yb;
    int   y1i = (yle >= FH - 1) ? (FH - 1) : (yle + 1);
    int   h = y1i - y0 + 1;      if (h > RROWS) h = RROWS;

    float xa = fmaxf(sw + 0.25f * bw, 0.0f);
    int   x0 = (int)xa;          if (x0 >= FW - 1) x0 = FW - 1;
    float xb = fmaxf(sw + 6.75f * bw, 0.0f);
    int   xle = (int)xb;
    int   x1i = (xle >= FW - 1) ? (FW - 1) : (xle + 1);

    const int x0a  = x0 & ~3;                 // 16B-aligned region start
    int       wext = x1i - x0a + 1;
    if (wext > RSTRIDE) wext = RSTRIDE;
    const int w4   = (wext + 3) >> 2;         // 16B chunks per row (<=7)

    // --- separable per-thread taps in registers ---
    int   yoff[4], xoff[4];
    float wy[4],   wx[4];
    const int c_sub = tid / OUTHW;            // 0..4 active (tid < 245)
    const int p     = tid - c_sub * OUTHW;
    const bool active = (tid < 5 * OUTHW);

    if (active) {
        const int ph = p / 7;
        const int pw = p - ph * 7;

        #pragma unroll
        for (int i = 0; i < 2; i++) {
            float y = sh + (float)ph * bh + ((float)i + 0.5f) * (bh * 0.5f);
            y = fmaxf(y, 0.0f);
            int yl = (int)y;
            int yh = (yl >= FH - 1) ? (FH - 1) : (yl + 1);
            yl     = (yl >= FH - 1) ? (FH - 1) : yl;
            float ly = y - (float)yl;
            yoff[2 * i + 0] = (yl - y0) * RSTRIDE;  wy[2 * i + 0] = 0.25f * (1.0f - ly);
            yoff[2 * i + 1] = (yh - y0) * RSTRIDE;  wy[2 * i + 1] = 0.25f * ly;

            float x = sw + (float)pw * bw + ((float)i + 0.5f) * (bw * 0.5f);
            x = fmaxf(x, 0.0f);
            int xl = (int)x;
            int xh = (xl >= FW - 1) ? (FW - 1) : (xl + 1);
            xl     = (xl >= FW - 1) ? (FW - 1) : xl;
            float lx = x - (float)xl;
            xoff[2 * i + 0] = xl - x0a;  wx[2 * i + 0] = 1.0f - lx;
            xoff[2 * i + 1] = xh - x0a;  wx[2 * i + 1] = lx;
        }
    }

    const float* fb = feat + (size_t)b * (FC * FH * FW)
                           + (size_t)cbase * (FH * FW) + y0 * FW + x0a;
    float*       ob = out  + (size_t)k * (FC * OUTHW) + cbase * OUTHW;

    // staging lane mapping: flatten (row, 16B-chunk) over 32 lanes
    const int r_init = lane / w4;
    const int c_init = lane - r_init * w4;
    const int q32    = 32 / w4;
    const int rem32  = 32 - q32 * w4;

    const uint32_t sbase  = (uint32_t)__cvta_generic_to_shared(&s_reg[0][0][0]);
    const uint32_t schan  = sbase + wid * (RROWS * RSTRIDE * 4);
    const uint32_t sbufsz = CHUNK * RROWS * RSTRIDE * 4;

    // --- stage one chunk: warp wid stages channel (cc*CHUNK + wid) ---
    auto stage = [&](int cc) {
        const float* g = fb + (size_t)(cc * CHUNK + wid) * (FH * FW);
        const uint32_t sb = schan + (cc & 1) * sbufsz;
        int r = r_init, c = c_init;
        #pragma unroll
        for (int it = 0; it < 6; it++) {
            if (r < h)
                cp16(sb + (r * (RSTRIDE * 4) + (c << 4)), g + r * FW + (c << 2));
            c += rem32;
            int carry = (c >= w4);
            r += q32 + carry;
            if (carry) c -= w4;
        }
        CP_COMMIT;
    };

    stage(0);

    #pragma unroll 1
    for (int cc = 0; cc < NCHUNK; cc++) {
        if (cc + 1 < NCHUNK) {
            stage(cc + 1);
            CP_WAIT(1);        // chunk cc complete
        } else {
            CP_WAIT(0);
        }
        __syncthreads();

        if (active) {
            const int buf = cc & 1;
            #pragma unroll
            for (int j = 0; j < 2; j++) {
                const int cl = c_sub + 5 * j;
                if (cl < CHUNK) {
                    const float* rg = &s_reg[buf][cl][0];
                    float acc = 0.0f;
                    #pragma unroll
                    for (int i = 0; i < 4; i++) {
                        const float* row = rg + yoff[i];
                        float rs;
                        rs = wx[0] * row[xoff[0]];
                        rs = fmaf(wx[1], row[xoff[1]], rs);
                        rs = fmaf(wx[2], row[xoff[2]], rs);
                        rs = fmaf(wx[3], row[xoff[3]], rs);
                        acc = fmaf(wy[i], rs, acc);
                    }
                    ob[(cc * CHUNK + cl) * OUTHW + p] = acc;
                }
            }
        }
        __syncthreads();       // buffer (cc&1) free for stage(cc+2)
    }
}

extern "C" void kernel_launch(void* const* d_in, const int* in_sizes, int n_in,
                              void* d_out, int out_size)
{
    const float* feat = (const float*)d_in[0];
    const float* rois = (const float*)d_in[1];
    float*       out  = (float*)d_out;

    cudaFuncSetAttribute(roialign_kernel,
                         cudaFuncAttributePreferredSharedMemoryCarveout, 100);

    const int K = in_sizes[1] / 5;  // 512
    dim3 grid(K, CSPLIT);
    roialign_kernel<<<grid, 256>>>(feat, rois, out);
}

// round 7
// speedup vs baseline: 1.8613x; 1.0006x over previous
#include <cuda_runtime.h>
#include <cuda_bf16.h>
#include <cstdint>

// RoIAlign: feat [4,256,100,100] f32, rois [512,5] f32 -> out [512,256,7,7] f32
// SPATIAL_SCALE=0.25, SAMPLING_RATIO=2, ALIGNED=true, OUT 7x7.
//
// One block per (RoI, channel-eighth). Region bbox <= 25x25, staged with 16B
// cp.async (x aligned down to 4 floats, row stride 28), double-buffered
// 8-channel chunks overlapped with compute. Separable taps (4 rows x 4 cols)
// in registers; __launch_bounds__(256,4) -> 64 regs -> 4 CTAs/SM.

#define FH 100
#define FW 100
#define FC 256
#define OUTHW 49
#define RROWS 25         // max region rows
#define RSTRIDE 28       // region row stride in floats (mult of 4)
#define CHUNK 8          // channels per stage
#define CSPLIT 8         // channel-split blocks per RoI
#define CPB (FC / CSPLIT)     // 32 channels per block
#define NCHUNK (CPB / CHUNK)  // 4

#define CP_COMMIT asm volatile("cp.async.commit_group;\n" ::)
#define CP_WAIT(n) asm volatile("cp.async.wait_group %0;\n" :: "n"(n))

__device__ __forceinline__ void cp16(uint32_t saddr, const float* g) {
    asm volatile("cp.async.cg.shared.global [%0], [%1], 16;\n" :: "r"(saddr), "l"(g));
}

__global__ __launch_bounds__(256, 4) void roialign_kernel(
    const float* __restrict__ feat,
    const float* __restrict__ rois,
    float* __restrict__ out)
{
    __shared__ float s_reg[2][CHUNK][RROWS * RSTRIDE];  // 44800 B

    const int k     = blockIdx.x;
    const int cbase = blockIdx.y * CPB;
    const int tid   = threadIdx.x;
    const int wid   = tid >> 5;
    const int lane  = tid & 31;

    // --- RoI params (broadcast) ---
    const int   b  = (int)__ldg(rois + k * 5 + 0);
    const float x1 = __ldg(rois + k * 5 + 1);
    const float y1 = __ldg(rois + k * 5 + 2);
    const float x2 = __ldg(rois + k * 5 + 3);
    const float y2 = __ldg(rois + k * 5 + 4);

    const float sw = x1 * 0.25f - 0.5f;
    const float sh = y1 * 0.25f - 0.5f;
    const float bw = (x2 * 0.25f - 0.5f - sw) * (1.0f / 7.0f);
    const float bh = (y2 * 0.25f - 0.5f - sh) * (1.0f / 7.0f);

    // --- region bounds (samples monotone in ph/pw) ---
    float ya = fmaxf(sh + 0.25f * bh, 0.0f);
    int   y0 = (int)ya;          if (y0 >= FH - 1) y0 = FH - 1;
    float yb = fmaxf(sh + 6.75f * bh, 0.0f);
    int   yle = (int)yb;
    int   y1i = (yle >= FH - 1) ? (FH - 1) : (yle + 1);
    int   h = y1i - y0 + 1;      if (h > RROWS) h = RROWS;

    float xa = fmaxf(sw + 0.25f * bw, 0.0f);
    int   x0 = (int)xa;          if (x0 >= FW - 1) x0 = FW - 1;
    float xb = fmaxf(sw + 6.75f * bw, 0.0f);
    int   xle = (int)xb;
    int   x1i = (xle >= FW - 1) ? (FW - 1) : (xle + 1);

    const int x0a  = x0 & ~3;                 // 16B-aligned region start
    int       wext = x1i - x0a + 1;
    if (wext > RSTRIDE) wext = RSTRIDE;
    const int w4   = (wext + 3) >> 2;         // 16B chunks per row (<=7)

    // --- separable per-thread taps in registers ---
    int   yoff[4], xoff[4];
    float wy[4],   wx[4];
    const int c_sub = tid / OUTHW;            // 0..4 active (tid < 245)
    const int p     = tid - c_sub * OUTHW;
    const bool active = (tid < 5 * OUTHW);

    if (active) {
        const int ph = p / 7;
        const int pw = p - ph * 7;

        #pragma unroll
        for (int i = 0; i < 2; i++) {
            float y = sh + (float)ph * bh + ((float)i + 0.5f) * (bh * 0.5f);
            y = fmaxf(y, 0.0f);
            int yl = (int)y;
            int yh = (yl >= FH - 1) ? (FH - 1) : (yl + 1);
            yl     = (yl >= FH - 1) ? (FH - 1) : yl;
            float ly = y - (float)yl;
            yoff[2 * i + 0] = (yl - y0) * RSTRIDE;  wy[2 * i + 0] = 0.25f * (1.0f - ly);
            yoff[2 * i + 1] = (yh - y0) * RSTRIDE;  wy[2 * i + 1] = 0.25f * ly;

            float x = sw + (float)pw * bw + ((float)i + 0.5f) * (bw * 0.5f);
            x = fmaxf(x, 0.0f);
            int xl = (int)x;
            int xh = (xl >= FW - 1) ? (FW - 1) : (xl + 1);
            xl     = (xl >= FW - 1) ? (FW - 1) : xl;
            float lx = x - (float)xl;
            xoff[2 * i + 0] = xl - x0a;  wx[2 * i + 0] = 1.0f - lx;
            xoff[2 * i + 1] = xh - x0a;  wx[2 * i + 1] = lx;
        }
    }

    const float* fb = feat + (size_t)b * (FC * FH * FW)
                           + (size_t)cbase * (FH * FW) + y0 * FW + x0a;
    float*       ob = out  + (size_t)k * (FC * OUTHW) + cbase * OUTHW;

    // staging lane mapping: flatten (row, 16B-chunk) over 32 lanes
    const int r_init = lane / w4;
    const int c_init = lane - r_init * w4;
    const int q32    = 32 / w4;
    const int rem32  = 32 - q32 * w4;

    const uint32_t sbase  = (uint32_t)__cvta_generic_to_shared(&s_reg[0][0][0]);
    const uint32_t schan  = sbase + wid * (RROWS * RSTRIDE * 4);
    const uint32_t sbufsz = CHUNK * RROWS * RSTRIDE * 4;

    // --- stage one chunk: warp wid stages channel (cc*CHUNK + wid) ---
    auto stage = [&](int cc) {
        const float* g = fb + (size_t)(cc * CHUNK + wid) * (FH * FW);
        const uint32_t sb = schan + (cc & 1) * sbufsz;
        int r = r_init, c = c_init;
        #pragma unroll
        for (int it = 0; it < 6; it++) {
            if (r < h)
                cp16(sb + (r * (RSTRIDE * 4) + (c << 4)), g + r * FW + (c << 2));
            c += rem32;
            int carry = (c >= w4);
            r += q32 + carry;
            if (carry) c -= w4;
        }
        CP_COMMIT;
    };

    stage(0);

    #pragma unroll 1
    for (int cc = 0; cc < NCHUNK; cc++) {
        if (cc + 1 < NCHUNK) {
            stage(cc + 1);
            CP_WAIT(1);        // chunk cc complete
        } else {
            CP_WAIT(0);
        }
        __syncthreads();

        if (active) {
            const int buf = cc & 1;
            #pragma unroll
            for (int j = 0; j < 2; j++) {
                const int cl = c_sub + 5 * j;
                if (cl < CHUNK) {
                    const float* rg = &s_reg[buf][cl][0];
                    float acc = 0.0f;
                    #pragma unroll
                    for (int i = 0; i < 4; i++) {
                        const float* row = rg + yoff[i];
                        float rs;
                        rs = wx[0] * row[xoff[0]];
                        rs = fmaf(wx[1], row[xoff[1]], rs);
                        rs = fmaf(wx[2], row[xoff[2]], rs);
                        rs = fmaf(wx[3], row[xoff[3]], rs);
                        acc = fmaf(wy[i], rs, acc);
                    }
                    ob[(cc * CHUNK + cl) * OUTHW + p] = acc;
                }
            }
        }
        __syncthreads();       // buffer (cc&1) free for stage(cc+2)
    }
}

extern "C" void kernel_launch(void* const* d_in, const int* in_sizes, int n_in,
                              void* d_out, int out_size)
{
    const float* feat = (const float*)d_in[0];
    const float* rois = (const float*)d_in[1];
    float*       out  = (float*)d_out;

    cudaFuncSetAttribute(roialign_kernel,
                         cudaFuncAttributePreferredSharedMemoryCarveout, 100);

    const int K = in_sizes[1] / 5;  // 512
    dim3 grid(K, CSPLIT);
    roialign_kernel<<<grid, 256>>>(feat, rois, out);
}

// round 8
// speedup vs baseline: 1.9269x; 1.0353x over previous
#include <cuda_runtime.h>
#include <cuda_bf16.h>
#include <cstdint>

// RoIAlign: feat [4,256,100,100] f32, rois [512,5] f32 -> out [512,256,7,7] f32
// SPATIAL_SCALE=0.25, SAMPLING_RATIO=2, ALIGNED=true, OUT 7x7.
//
// Warp-pair pipelines: each 64-thread pair stages (16B cp.async, double
// buffer) and computes its own channels; sync = wait_group + 64-thread named
// barrier. No CTA-wide barriers. 4 pairs/block, 16 channels/block, grid
// (512,16). SMEM 22.4KB, 5 CTAs/SM.

#define FH 100
#define FW 100
#define FC 256
#define OUTHW 49
#define RROWS 25          // max region rows
#define RSTRIDE 28        // region row stride in floats (mult of 4)
#define PAIRS 4           // warp pairs per block
#define CSPLIT 16         // channel-split blocks per RoI
#define CPB (FC / CSPLIT) // 16 channels per block
#define CPP (CPB / PAIRS) // 4 channels per pair

#define CP_COMMIT asm volatile("cp.async.commit_group;\n" ::)
#define CP_WAIT(n) asm volatile("cp.async.wait_group %0;\n" :: "n"(n))
#define BAR64(id) asm volatile("bar.sync %0, 64;\n" :: "r"(id) : "memory")

__device__ __forceinline__ void cp16(uint32_t saddr, const float* g) {
    asm volatile("cp.async.cg.shared.global [%0], [%1], 16;\n" :: "r"(saddr), "l"(g));
}

__global__ __launch_bounds__(256, 5) void roialign_kernel(
    const float* __restrict__ feat,
    const float* __restrict__ rois,
    float* __restrict__ out)
{
    __shared__ float s_reg[PAIRS][2][RROWS * RSTRIDE];  // 22400 B

    const int k      = blockIdx.x;
    const int cbase  = blockIdx.y * CPB;
    const int tid    = threadIdx.x;
    const int wid    = tid >> 5;
    const int lane   = tid & 31;
    const int pair   = wid >> 1;
    const int lane64 = ((wid & 1) << 5) + lane;   // 0..63 within pair

    // --- RoI params (broadcast) ---
    const int   b  = (int)__ldg(rois + k * 5 + 0);
    const float x1 = __ldg(rois + k * 5 + 1);
    const float y1 = __ldg(rois + k * 5 + 2);
    const float x2 = __ldg(rois + k * 5 + 3);
    const float y2 = __ldg(rois + k * 5 + 4);

    const float sw = x1 * 0.25f - 0.5f;
    const float sh = y1 * 0.25f - 0.5f;
    const float bw = (x2 * 0.25f - 0.5f - sw) * (1.0f / 7.0f);
    const float bh = (y2 * 0.25f - 0.5f - sh) * (1.0f / 7.0f);

    // --- region bounds (samples monotone in ph/pw) ---
    float ya = fmaxf(sh + 0.25f * bh, 0.0f);
    int   y0 = (int)ya;          if (y0 >= FH - 1) y0 = FH - 1;
    float yb = fmaxf(sh + 6.75f * bh, 0.0f);
    int   yle = (int)yb;
    int   y1i = (yle >= FH - 1) ? (FH - 1) : (yle + 1);
    int   h = y1i - y0 + 1;      if (h > RROWS) h = RROWS;

    float xa = fmaxf(sw + 0.25f * bw, 0.0f);
    int   x0 = (int)xa;          if (x0 >= FW - 1) x0 = FW - 1;
    float xb = fmaxf(sw + 6.75f * bw, 0.0f);
    int   xle = (int)xb;
    int   x1i = (xle >= FW - 1) ? (FW - 1) : (xle + 1);

    const int x0a  = x0 & ~3;                 // 16B-aligned region start
    int       wext = x1i - x0a + 1;
    if (wext > RSTRIDE) wext = RSTRIDE;
    const int w4   = (wext + 3) >> 2;         // 16B chunks per row (<=7)

    // --- separable taps for this thread's pixel p = lane64 ---
    int   yoff[4], xoff[4];
    float wy[4],   wx[4];
    const int  p      = lane64;
    const bool active = (p < OUTHW);

    if (active) {
        const int ph = p / 7;
        const int pw = p - ph * 7;

        #pragma unroll
        for (int i = 0; i < 2; i++) {
            float y = sh + (float)ph * bh + ((float)i + 0.5f) * (bh * 0.5f);
            y = fmaxf(y, 0.0f);
            int yl = (int)y;
            int yh = (yl >= FH - 1) ? (FH - 1) : (yl + 1);
            yl     = (yl >= FH - 1) ? (FH - 1) : yl;
            float ly = y - (float)yl;
            yoff[2 * i + 0] = (yl - y0) * RSTRIDE;  wy[2 * i + 0] = 0.25f * (1.0f - ly);
            yoff[2 * i + 1] = (yh - y0) * RSTRIDE;  wy[2 * i + 1] = 0.25f * ly;

            float x = sw + (float)pw * bw + ((float)i + 0.5f) * (bw * 0.5f);
            x = fmaxf(x, 0.0f);
            int xl = (int)x;
            int xh = (xl >= FW - 1) ? (FW - 1) : (xl + 1);
            xl     = (xl >= FW - 1) ? (FW - 1) : xl;
            float lx = x - (float)xl;
            xoff[2 * i + 0] = xl - x0a;  wx[2 * i + 0] = 1.0f - lx;
            xoff[2 * i + 1] = xh - x0a;  wx[2 * i + 1] = lx;
        }
    }

    const float* fb = feat + (size_t)b * (FC * FH * FW)
                           + (size_t)cbase * (FH * FW) + y0 * FW + x0a;
    float*       ob = out  + (size_t)k * (FC * OUTHW) + cbase * OUTHW;

    // staging lane mapping: flatten (row, 16B-chunk) over 64 lanes
    // max chunks = 25*7 = 175 <= 64*3
    const int r_init = lane64 / w4;
    const int c_init = lane64 - r_init * w4;
    const int q64    = 64 / w4;
    const int rem64  = 64 - q64 * w4;

    const uint32_t s0 = (uint32_t)__cvta_generic_to_shared(&s_reg[pair][0][0]);
    const uint32_t sbufsz = RROWS * RSTRIDE * 4;

    // channel i of this pair = cbase + pair + PAIRS*i
    auto stage = [&](int i) {
        const float* g = fb + (size_t)(pair + PAIRS * i) * (FH * FW);
        const uint32_t sb = s0 + (uint32_t)(i & 1) * sbufsz;
        int r = r_init, c = c_init;
        #pragma unroll
        for (int it = 0; it < 3; it++) {
            if (r < h)
                cp16(sb + (r * (RSTRIDE * 4) + (c << 4)), g + r * FW + (c << 2));
            c += rem64;
            int carry = (c >= w4);
            r += q64 + carry;
            if (carry) c -= w4;
        }
        CP_COMMIT;
    };

    stage(0);
    stage(1);

    const int barid = pair + 1;   // named barriers 1..4 (0 reserved)

    #pragma unroll
    for (int i = 0; i < CPP; i++) {
        if (i < CPP - 1) { CP_WAIT(1); } else { CP_WAIT(0); }
        BAR64(barid);     // all 64 lanes' cp.async for channel i visible

        if (active) {
            const float* rg = &s_reg[pair][i & 1][0];
            float acc = 0.0f;
            #pragma unroll
            for (int r4 = 0; r4 < 4; r4++) {
                const float* row = rg + yoff[r4];
                float rs;
                rs = wx[0] * row[xoff[0]];
                rs = fmaf(wx[1], row[xoff[1]], rs);
                rs = fmaf(wx[2], row[xoff[2]], rs);
                rs = fmaf(wx[3], row[xoff[3]], rs);
                acc = fmaf(wy[r4], rs, acc);
            }
            ob[(pair + PAIRS * i) * OUTHW + p] = acc;
        }

        if (i + 2 < CPP) {
            BAR64(barid); // both warps done reading buf (i&1) before restaging
            stage(i + 2);
        }
    }
}

extern "C" void kernel_launch(void* const* d_in, const int* in_sizes, int n_in,
                              void* d_out, int out_size)
{
    const float* feat = (const float*)d_in[0];
    const float* rois = (const float*)d_in[1];
    float*       out  = (float*)d_out;

    cudaFuncSetAttribute(roialign_kernel,
                         cudaFuncAttributePreferredSharedMemoryCarveout, 100);

    const int K = in_sizes[1] / 5;  // 512
    dim3 grid(K, CSPLIT);
    roialign_kernel<<<grid, 256>>>(feat, rois, out);
}

// round 9
// speedup vs baseline: 1.9282x; 1.0006x over previous
#include <cuda_runtime.h>
#include <cuda_bf16.h>
#include <cstdint>

// RoIAlign: feat [4,256,100,100] f32, rois [512,5] f32 -> out [512,256,7,7] f32
// SPATIAL_SCALE=0.25, SAMPLING_RATIO=2, ALIGNED=true, OUT 7x7.
//
// Warp-pair pipelines: each 64-thread pair stages (16B cp.async, double
// buffer) and computes its own channels; sync = wait_group + 64-thread named
// barrier. No CTA-wide barriers. 4 pairs/block, 16 channels/block, grid
// (512,16). SMEM 22.4KB, 5 CTAs/SM.

#define FH 100
#define FW 100
#define FC 256
#define OUTHW 49
#define RROWS 25          // max region rows
#define RSTRIDE 28        // region row stride in floats (mult of 4)
#define PAIRS 4           // warp pairs per block
#define CSPLIT 16         // channel-split blocks per RoI
#define CPB (FC / CSPLIT) // 16 channels per block
#define CPP (CPB / PAIRS) // 4 channels per pair

#define CP_COMMIT asm volatile("cp.async.commit_group;\n" ::)
#define CP_WAIT(n) asm volatile("cp.async.wait_group %0;\n" :: "n"(n))
#define BAR64(id) asm volatile("bar.sync %0, 64;\n" :: "r"(id) : "memory")

__device__ __forceinline__ void cp16(uint32_t saddr, const float* g) {
    asm volatile("cp.async.cg.shared.global [%0], [%1], 16;\n" :: "r"(saddr), "l"(g));
}

__global__ __launch_bounds__(256, 5) void roialign_kernel(
    const float* __restrict__ feat,
    const float* __restrict__ rois,
    float* __restrict__ out)
{
    __shared__ float s_reg[PAIRS][2][RROWS * RSTRIDE];  // 22400 B

    const int k      = blockIdx.x;
    const int cbase  = blockIdx.y * CPB;
    const int tid    = threadIdx.x;
    const int wid    = tid >> 5;
    const int lane   = tid & 31;
    const int pair   = wid >> 1;
    const int lane64 = ((wid & 1) << 5) + lane;   // 0..63 within pair

    // --- RoI params (broadcast) ---
    const int   b  = (int)__ldg(rois + k * 5 + 0);
    const float x1 = __ldg(rois + k * 5 + 1);
    const float y1 = __ldg(rois + k * 5 + 2);
    const float x2 = __ldg(rois + k * 5 + 3);
    const float y2 = __ldg(rois + k * 5 + 4);

    const float sw = x1 * 0.25f - 0.5f;
    const float sh = y1 * 0.25f - 0.5f;
    const float bw = (x2 * 0.25f - 0.5f - sw) * (1.0f / 7.0f);
    const float bh = (y2 * 0.25f - 0.5f - sh) * (1.0f / 7.0f);

    // --- region bounds (samples monotone in ph/pw) ---
    float ya = fmaxf(sh + 0.25f * bh, 0.0f);
    int   y0 = (int)ya;          if (y0 >= FH - 1) y0 = FH - 1;
    float yb = fmaxf(sh + 6.75f * bh, 0.0f);
    int   yle = (int)yb;
    int   y1i = (yle >= FH - 1) ? (FH - 1) : (yle + 1);
    int   h = y1i - y0 + 1;      if (h > RROWS) h = RROWS;

    float xa = fmaxf(sw + 0.25f * bw, 0.0f);
    int   x0 = (int)xa;          if (x0 >= FW - 1) x0 = FW - 1;
    float xb = fmaxf(sw + 6.75f * bw, 0.0f);
    int   xle = (int)xb;
    int   x1i = (xle >= FW - 1) ? (FW - 1) : (xle + 1);

    const int x0a  = x0 & ~3;                 // 16B-aligned region start
    int       wext = x1i - x0a + 1;
    if (wext > RSTRIDE) wext = RSTRIDE;
    const int w4   = (wext + 3) >> 2;         // 16B chunks per row (<=7)

    // --- separable taps for this thread's pixel p = lane64 ---
    int   yoff[4], xoff[4];
    float wy[4],   wx[4];
    const int  p      = lane64;
    const bool active = (p < OUTHW);

    if (active) {
        const int ph = p / 7;
        const int pw = p - ph * 7;

        #pragma unroll
        for (int i = 0; i < 2; i++) {
            float y = sh + (float)ph * bh + ((float)i + 0.5f) * (bh * 0.5f);
            y = fmaxf(y, 0.0f);
            int yl = (int)y;
            int yh = (yl >= FH - 1) ? (FH - 1) : (yl + 1);
            yl     = (yl >= FH - 1) ? (FH - 1) : yl;
            float ly = y - (float)yl;
            yoff[2 * i + 0] = (yl - y0) * RSTRIDE;  wy[2 * i + 0] = 0.25f * (1.0f - ly);
            yoff[2 * i + 1] = (yh - y0) * RSTRIDE;  wy[2 * i + 1] = 0.25f * ly;

            float x = sw + (float)pw * bw + ((float)i + 0.5f) * (bw * 0.5f);
            x = fmaxf(x, 0.0f);
            int xl = (int)x;
            int xh = (xl >= FW - 1) ? (FW - 1) : (xl + 1);
            xl     = (xl >= FW - 1) ? (FW - 1) : xl;
            float lx = x - (float)xl;
            xoff[2 * i + 0] = xl - x0a;  wx[2 * i + 0] = 1.0f - lx;
            xoff[2 * i + 1] = xh - x0a;  wx[2 * i + 1] = lx;
        }
    }

    const float* fb = feat + (size_t)b * (FC * FH * FW)
                           + (size_t)cbase * (FH * FW) + y0 * FW + x0a;
    float*       ob = out  + (size_t)k * (FC * OUTHW) + cbase * OUTHW;

    // staging lane mapping: flatten (row, 16B-chunk) over 64 lanes
    // max chunks = 25*7 = 175 <= 64*3
    const int r_init = lane64 / w4;
    const int c_init = lane64 - r_init * w4;
    const int q64    = 64 / w4;
    const int rem64  = 64 - q64 * w4;

    const uint32_t s0 = (uint32_t)__cvta_generic_to_shared(&s_reg[pair][0][0]);
    const uint32_t sbufsz = RROWS * RSTRIDE * 4;

    // channel i of this pair = cbase + pair + PAIRS*i
    auto stage = [&](int i) {
        const float* g = fb + (size_t)(pair + PAIRS * i) * (FH * FW);
        const uint32_t sb = s0 + (uint32_t)(i & 1) * sbufsz;
        int r = r_init, c = c_init;
        #pragma unroll
        for (int it = 0; it < 3; it++) {
            if (r < h)
                cp16(sb + (r * (RSTRIDE * 4) + (c << 4)), g + r * FW + (c << 2));
            c += rem64;
            int carry = (c >= w4);
            r += q64 + carry;
            if (carry) c -= w4;
        }
        CP_COMMIT;
    };

    stage(0);
    stage(1);

    const int barid = pair + 1;   // named barriers 1..4 (0 reserved)

    #pragma unroll
    for (int i = 0; i < CPP; i++) {
        if (i < CPP - 1) { CP_WAIT(1); } else { CP_WAIT(0); }
        BAR64(barid);     // all 64 lanes' cp.async for channel i visible

        if (active) {
            const float* rg = &s_reg[pair][i & 1][0];
            float acc = 0.0f;
            #pragma unroll
            for (int r4 = 0; r4 < 4; r4++) {
                const float* row = rg + yoff[r4];
                float rs;
                rs = wx[0] * row[xoff[0]];
                rs = fmaf(wx[1], row[xoff[1]], rs);
                rs = fmaf(wx[2], row[xoff[2]], rs);
                rs = fmaf(wx[3], row[xoff[3]], rs);
                acc = fmaf(wy[r4], rs, acc);
            }
            ob[(pair + PAIRS * i) * OUTHW + p] = acc;
        }

        if (i + 2 < CPP) {
            BAR64(barid); // both warps done reading buf (i&1) before restaging
            stage(i + 2);
        }
    }
}

extern "C" void kernel_launch(void* const* d_in, const int* in_sizes, int n_in,
                              void* d_out, int out_size)
{
    const float* feat = (const float*)d_in[0];
    const float* rois = (const float*)d_in[1];
    float*       out  = (float*)d_out;

    cudaFuncSetAttribute(roialign_kernel,
                         cudaFuncAttributePreferredSharedMemoryCarveout, 100);

    const int K = in_sizes[1] / 5;  // 512
    dim3 grid(K, CSPLIT);
    roialign_kernel<<<grid, 256>>>(feat, rois, out);
}

// round 10
// speedup vs baseline: 2.0202x; 1.0477x over previous
#include <cuda_runtime.h>
#include <cuda_bf16.h>
#include <cstdint>

// RoIAlign: feat [4,256,100,100] f32, rois [512,5] f32 -> out [512,256,7,7] f32
// SPATIAL_SCALE=0.25, SAMPLING_RATIO=2, ALIGNED=true, OUT 7x7.
//
// Warp-pair pipelines: each 64-thread pair stages (16B cp.async, double
// buffer) and computes its own 8 channels; sync = wait_group + 64-thread
// named barrier. Taps precomputed as ABSOLUTE smem addresses (buffer 0);
// buffer 1 accessed via the +2800 immediate on ld.shared -> zero-ALU inner
// loop. 4 pairs/block, 32 channels/block, grid (512,8).

#define FH 100
#define FW 100
#define FC 256
#define OUTHW 49
#define RROWS 25          // max region rows
#define RSTRIDE 28        // region row stride in floats (mult of 4)
#define PAIRS 4           // warp pairs per block
#define CSPLIT 8          // channel-split blocks per RoI
#define CPB (FC / CSPLIT) // 32 channels per block
#define CPP (CPB / PAIRS) // 8 channels per pair
#define BUFB (RROWS * RSTRIDE * 4)  // 2800 bytes per buffer

#define CP_COMMIT asm volatile("cp.async.commit_group;\n" ::)
#define CP_WAIT(n) asm volatile("cp.async.wait_group %0;\n" :: "n"(n))
#define BAR64(id) asm volatile("bar.sync %0, 64;\n" :: "r"(id) : "memory")

__device__ __forceinline__ void cp16(uint32_t saddr, const float* g) {
    asm volatile("cp.async.cg.shared.global [%0], [%1], 16;\n" :: "r"(saddr), "l"(g));
}
__device__ __forceinline__ float lds0(uint32_t a) {
    float v; asm volatile("ld.shared.f32 %0, [%1];" : "=f"(v) : "r"(a)); return v;
}
__device__ __forceinline__ float lds1(uint32_t a) {
    float v; asm volatile("ld.shared.f32 %0, [%1+2800];" : "=f"(v) : "r"(a)); return v;
}

__global__ __launch_bounds__(256, 4) void roialign_kernel(
    const float* __restrict__ feat,
    const float* __restrict__ rois,
    float* __restrict__ out)
{
    __shared__ float s_reg[PAIRS][2][RROWS * RSTRIDE];  // 22400 B

    const int k      = blockIdx.x;
    const int cbase  = blockIdx.y * CPB;
    const int tid    = threadIdx.x;
    const int wid    = tid >> 5;
    const int lane   = tid & 31;
    const int pair   = wid >> 1;
    const int lane64 = ((wid & 1) << 5) + lane;   // 0..63 within pair

    // --- RoI params (broadcast) ---
    const int   b  = (int)__ldg(rois + k * 5 + 0);
    const float x1 = __ldg(rois + k * 5 + 1);
    const float y1 = __ldg(rois + k * 5 + 2);
    const float x2 = __ldg(rois + k * 5 + 3);
    const float y2 = __ldg(rois + k * 5 + 4);

    const float sw = x1 * 0.25f - 0.5f;
    const float sh = y1 * 0.25f - 0.5f;
    const float bw = (x2 * 0.25f - 0.5f - sw) * (1.0f / 7.0f);
    const float bh = (y2 * 0.25f - 0.5f - sh) * (1.0f / 7.0f);

    // --- region bounds (samples monotone in ph/pw) ---
    float ya = fmaxf(sh + 0.25f * bh, 0.0f);
    int   y0 = (int)ya;          if (y0 >= FH - 1) y0 = FH - 1;
    float yb = fmaxf(sh + 6.75f * bh, 0.0f);
    int   yle = (int)yb;
    int   y1i = (yle >= FH - 1) ? (FH - 1) : (yle + 1);
    int   h = y1i - y0 + 1;      if (h > RROWS) h = RROWS;

    float xa = fmaxf(sw + 0.25f * bw, 0.0f);
    int   x0 = (int)xa;          if (x0 >= FW - 1) x0 = FW - 1;
    float xb = fmaxf(sw + 6.75f * bw, 0.0f);
    int   xle = (int)xb;
    int   x1i = (xle >= FW - 1) ? (FW - 1) : (xle + 1);

    const int x0a  = x0 & ~3;                 // 16B-aligned region start
    int       wext = x1i - x0a + 1;
    if (wext > RSTRIDE) wext = RSTRIDE;
    const int w4   = (wext + 3) >> 2;         // 16B chunks per row (<=7)

    const uint32_t s0 = (uint32_t)__cvta_generic_to_shared(&s_reg[pair][0][0]);

    // --- taps as absolute smem addresses into buffer 0 ---
    uint32_t a16[16];
    float    wy[4], wx[4];
    const int  p      = lane64;
    const bool active = (p < OUTHW);

    if (active) {
        const int ph = p / 7;
        const int pw = p - ph * 7;
        int yoff[4], xoff[4];

        #pragma unroll
        for (int i = 0; i < 2; i++) {
            float y = sh + (float)ph * bh + ((float)i + 0.5f) * (bh * 0.5f);
            y = fmaxf(y, 0.0f);
            int yl = (int)y;
            int yh = (yl >= FH - 1) ? (FH - 1) : (yl + 1);
            yl     = (yl >= FH - 1) ? (FH - 1) : yl;
            float ly = y - (float)yl;
            yoff[2 * i + 0] = (yl - y0) * RSTRIDE;  wy[2 * i + 0] = 0.25f * (1.0f - ly);
            yoff[2 * i + 1] = (yh - y0) * RSTRIDE;  wy[2 * i + 1] = 0.25f * ly;

            float x = sw + (float)pw * bw + ((float)i + 0.5f) * (bw * 0.5f);
            x = fmaxf(x, 0.0f);
            int xl = (int)x;
            int xh = (xl >= FW - 1) ? (FW - 1) : (xl + 1);
            xl     = (xl >= FW - 1) ? (FW - 1) : xl;
            float lx = x - (float)xl;
            xoff[2 * i + 0] = xl - x0a;  wx[2 * i + 0] = 1.0f - lx;
            xoff[2 * i + 1] = xh - x0a;  wx[2 * i + 1] = lx;
        }

        #pragma unroll
        for (int r4 = 0; r4 < 4; r4++)
            #pragma unroll
            for (int cx = 0; cx < 4; cx++)
                a16[r4 * 4 + cx] = s0 + (uint32_t)((yoff[r4] + xoff[cx]) << 2);
    }

    const float* fb = feat + (size_t)b * (FC * FH * FW)
                           + (size_t)cbase * (FH * FW) + y0 * FW + x0a;
    float*       ob = out  + (size_t)k * (FC * OUTHW) + cbase * OUTHW;

    // staging lane mapping: flatten (row, 16B-chunk) over 64 lanes
    const int r_init = lane64 / w4;
    const int c_init = lane64 - r_init * w4;
    const int q64    = 64 / w4;
    const int rem64  = 64 - q64 * w4;

    // channel i of this pair = cbase + pair + PAIRS*i
    auto stage = [&](int i) {
        const float* g = fb + (size_t)(pair + PAIRS * i) * (FH * FW);
        const uint32_t sb = s0 + (uint32_t)(i & 1) * BUFB;
        int r = r_init, c = c_init;
        #pragma unroll
        for (int it = 0; it < 3; it++) {
            if (r < h)
                cp16(sb + (r * (RSTRIDE * 4) + (c << 4)), g + r * FW + (c << 2));
            c += rem64;
            int carry = (c >= w4);
            r += q64 + carry;
            if (carry) c -= w4;
        }
        CP_COMMIT;
    };

    stage(0);
    stage(1);

    const int barid = pair + 1;   // named barriers 1..4 (0 reserved)

    #pragma unroll
    for (int i = 0; i < CPP; i++) {
        if (i < CPP - 1) { CP_WAIT(1); } else { CP_WAIT(0); }
        BAR64(barid);     // channel i's cp.async visible to both warps

        if (active) {
            float acc = 0.0f;
            if ((i & 1) == 0) {           // buffer 0 (i is a literal after unroll)
                #pragma unroll
                for (int r4 = 0; r4 < 4; r4++) {
                    float rs;
                    rs = wx[0] * lds0(a16[r4 * 4 + 0]);
                    rs = fmaf(wx[1], lds0(a16[r4 * 4 + 1]), rs);
                    rs = fmaf(wx[2], lds0(a16[r4 * 4 + 2]), rs);
                    rs = fmaf(wx[3], lds0(a16[r4 * 4 + 3]), rs);
                    acc = fmaf(wy[r4], rs, acc);
                }
            } else {                      // buffer 1 via +2800 immediate
                #pragma unroll
                for (int r4 = 0; r4 < 4; r4++) {
                    float rs;
                    rs = wx[0] * lds1(a16[r4 * 4 + 0]);
                    rs = fmaf(wx[1], lds1(a16[r4 * 4 + 1]), rs);
                    rs = fmaf(wx[2], lds1(a16[r4 * 4 + 2]), rs);
                    rs = fmaf(wx[3], lds1(a16[r4 * 4 + 3]), rs);
                    acc = fmaf(wy[r4], rs, acc);
                }
            }
            ob[(pair + PAIRS * i) * OUTHW + p] = acc;
        }

        if (i + 2 < CPP) {
            BAR64(barid); // both warps done reading buf (i&1) before restaging
            stage(i + 2);
        }
    }
}

extern "C" void kernel_launch(void* const* d_in, const int* in_sizes, int n_in,
                              void* d_out, int out_size)
{
    const float* feat = (const float*)d_in[0];
    const float* rois = (const float*)d_in[1];
    float*       out  = (float*)d_out;

    cudaFuncSetAttribute(roialign_kernel,
                         cudaFuncAttributePreferredSharedMemoryCarveout, 100);

    const int K = in_sizes[1] / 5;  // 512
    dim3 grid(K, CSPLIT);
    roialign_kernel<<<grid, 256>>>(feat, rois, out);
}